// round 11
// baseline (speedup 1.0000x reference)
#include <cuda_runtime.h>
#include <math.h>
#include <stdint.h>

#define NB 16
#define NN 32767
#define HD 128

// Fragment-packed tf32 weights in GLOBAL, layout [kg][nb][lane][2]:
//   elem[((kg*NBLK + nb)*32 + lane)*2 + p] = W[kg*8 + (lane&3) + 4p][col(nb,lane>>2)]
// d_Uf, d_W0 (NBLK=32): col = pairwise INTERLEAVE of (j, 128+j):  cI=2j / 2j+1
// d_Uh (NBLK=16):       col = within each 8-block, physical w holds logical (w>>1)+4(w&1)
__device__ float d_Uf[256 * 256];   // kg 0..31
__device__ float d_Uh[256 * 128];   // kg 0..31
__device__ float d_W0[128 * 256];   // kg 0..15

__device__ __forceinline__ float sigm(float v) { return 1.f / (1.f + expf(-v)); }
__device__ __forceinline__ float tf32r(float x) {
    float r; asm("cvt.rna.tf32.f32 %0, %1;" : "=f"(r) : "f"(x)); return r;
}
__device__ __forceinline__ void mma8(float* d, const uint32_t* a, const uint32_t* b) {
    asm volatile(
        "mma.sync.aligned.m16n8k8.row.col.f32.tf32.tf32.f32 "
        "{%0,%1,%2,%3}, {%4,%5,%6,%7}, {%8,%9}, {%0,%1,%2,%3};"
        : "+f"(d[0]), "+f"(d[1]), "+f"(d[2]), "+f"(d[3])
        : "r"(a[0]), "r"(a[1]), "r"(a[2]), "r"(a[3]), "r"(b[0]), "r"(b[1]));
}

// level smem (floats): sAf 16384 (A/g packed, 64 rows) | stg 8448 (out staging)
#define L_STG 16384
#define SMEM_LVL ((16384 + 8448) * 4)      // 99328 B -> 2 CTAs/SM @256thr
// init smem (floats): sAf 8192 | stg 8448
#define I_STG 8192
#define SMEM_INI ((8192 + 8448) * 4)       // 66560 B -> 2 CTAs/SM @512thr

// --------------------------------------------------------------------------
__global__ void prep_k(const float* __restrict__ Ww, const float* __restrict__ Ufw,
                       const float* __restrict__ Uhw)
{
    int i0 = blockIdx.x * blockDim.x + threadIdx.x, st = gridDim.x * blockDim.x;
    for (int idx = i0; idx < 131072; idx += st) {
        if (idx < 65536) {              // d_Uf (interleaved halves)
            int p = idx & 1, lane = (idx >> 1) & 31, nb = (idx >> 6) & 31, kg = idx >> 11;
            int k = kg * 8 + (lane & 3) + 4 * p;
            int cI = nb * 8 + (lane >> 2);
            int oc = (cI >> 1) + ((cI & 1) << 7);
            d_Uf[idx] = tf32r(Ufw[k * 256 + oc]);
        } else if (idx < 98304) {       // d_Uh (epilogue-matched permutation)
            int j = idx - 65536;
            int p = j & 1, lane = (j >> 1) & 31, nb = (j >> 6) & 15, kg = j >> 10;
            int k = kg * 8 + (lane & 3) + 4 * p;
            int w = lane >> 2;
            int n = nb * 8 + (w >> 1) + ((w & 1) << 2);
            d_Uh[j] = tf32r(Uhw[k * 128 + n]);
        } else {                        // d_W0 (interleaved halves)
            int j = idx - 98304;
            int p = j & 1, lane = (j >> 1) & 31, nb = (j >> 6) & 31, kg = j >> 11;
            int k = kg * 8 + (lane & 3) + 4 * p;
            int cI = nb * 8 + (lane >> 2);
            int oc = (cI >> 1) + ((cI & 1) << 7);
            d_W0[j] = tf32r(Ww[k * 256 + oc]);
        }
    }
}

// --------------------------------------------------------------------------
// Level kernel: 64 parents/CTA, 256 threads (8 warps; mt=4 M-tiles x 4 N-tiles).
// 2 CTAs/SM. fsum/gsum live in registers across both GEMMs.
// --------------------------------------------------------------------------
__global__ __launch_bounds__(256, 2) void level_mma_k(
    const float* __restrict__ Ufb, const float* __restrict__ Uhb,
    float* __restrict__ h, int start)
{
    extern __shared__ float sm[];
    float* sAf = sm;            // packed A/g fragments [rowblk(4)][kg(32)][lane(32)][4]
    float* stg = sm + L_STG;    // 64 x 132 output staging

    const int tid = threadIdx.x, lane = tid & 31, wn = tid >> 5;  // wn 0..7
    const int batch = blockIdx.y;
    const int node0 = start + blockIdx.x * 64;
    const float* hcg = h + ((size_t)batch * NN + 2 * node0 + 1) * HD;

    // load A = hc (64x256) into packed fragment layout, tf32-rounded
    for (int i = tid; i < 4096; i += 256) {
        float4 v = ((const float4*)hcg)[i];
        int r = i >> 6, c = (i & 63) << 2;
        int q = (((c & 7) >= 4) ? 2 : 0) + (((r & 15) >= 8) ? 1 : 0);
        float* dst = sAf + (((r >> 4) * 32 + (c >> 3)) * 32 + (r & 7) * 4) * 4 + q;
        dst[0]  = tf32r(v.x);
        dst[4]  = tf32r(v.y);
        dst[8]  = tf32r(v.z);
        dst[12] = tf32r(v.w);
    }
    __syncthreads();

    const int fr = lane >> 2, fc = lane & 3;

    // ---------------- phase 1: u = hc @ Uf (interleaved cols) ----------------
    float acc[4][4][4];
#pragma unroll
    for (int mt = 0; mt < 4; mt++)
#pragma unroll
        for (int nt = 0; nt < 4; nt++)
#pragma unroll
            for (int q = 0; q < 4; q++) acc[mt][nt][q] = 0.f;

#pragma unroll 2
    for (int kg = 0; kg < 32; kg++) {
        float4 av[4];
#pragma unroll
        for (int mt = 0; mt < 4; mt++)
            av[mt] = *(const float4*)(sAf + ((mt * 32 + kg) * 32 + lane) * 4);
#pragma unroll
        for (int nt = 0; nt < 4; nt++) {
            float2 bv = __ldg((const float2*)(d_Uf + ((kg * 32 + wn * 4 + nt) * 32 + lane) * 2));
#pragma unroll
            for (int mt = 0; mt < 4; mt++)
                mma8(acc[mt][nt], (const uint32_t*)&av[mt], (const uint32_t*)&bv);
        }
    }
    __syncthreads();   // phase-1 A reads complete before g overwrite

    // ---------------- epilogue 1: f, g, fsum/gsum (registers) ----------------
    float fs[4][4][2], gs[4][4][2];
#pragma unroll
    for (int nt = 0; nt < 4; nt++) {
        const int j = wn * 16 + nt * 4 + fc;
        const float bfA = __ldg(Ufb + j), bfB = __ldg(Ufb + 128 + j);
        const int kgA = j >> 3, khalf2 = ((j & 7) >= 4) ? 2 : 0;
#pragma unroll
        for (int mt = 0; mt < 4; mt++)
#pragma unroll
            for (int half = 0; half < 2; half++) {
                int r = mt * 16 + fr + half * 8;
                float fA = sigm(acc[mt][nt][half * 2] + bfA);
                float fB = sigm(acc[mt][nt][half * 2 + 1] + bfB);
                float hA = __ldg(hcg + r * 256 + j);
                float hB = __ldg(hcg + r * 256 + 128 + j);
                float gA = fA * hA, gB = fB * hB;
                int q = khalf2 + half;
                int base = (mt * 32) * 128 + lane * 4 + q;
                sAf[base + kgA * 128]        = tf32r(gA);
                sAf[base + (kgA + 16) * 128] = tf32r(gB);
                fs[mt][nt][half] = fA + fB;
                gs[mt][nt][half] = gA + gB;   // exact fp32
            }
    }
    __syncthreads();   // g visible to all warps

    // ---------------- phase 2: v = g @ Uh (permuted cols) ----------------
    float ac2[4][2][4];
#pragma unroll
    for (int mt = 0; mt < 4; mt++)
#pragma unroll
        for (int nt = 0; nt < 2; nt++)
#pragma unroll
            for (int q = 0; q < 4; q++) ac2[mt][nt][q] = 0.f;

#pragma unroll 2
    for (int kg = 0; kg < 32; kg++) {
        float4 av[4];
#pragma unroll
        for (int mt = 0; mt < 4; mt++)
            av[mt] = *(const float4*)(sAf + ((mt * 32 + kg) * 32 + lane) * 4);
#pragma unroll
        for (int nt = 0; nt < 2; nt++) {
            float2 bv = __ldg((const float2*)(d_Uh + ((kg * 16 + wn * 2 + nt) * 32 + lane) * 2));
#pragma unroll
            for (int mt = 0; mt < 4; mt++)
                mma8(ac2[mt][nt], (const uint32_t*)&av[mt], (const uint32_t*)&bv);
        }
    }

    // ---------------- epilogue 2 (ownership matches epilogue 1) -------------
    // ac2[mt][nt2] pair (d0,d1) = logical cols (j0, j0+4), j0 = wn*16+nt2*8+fc.
#pragma unroll
    for (int mt = 0; mt < 4; mt++)
#pragma unroll
        for (int nt2 = 0; nt2 < 2; nt2++) {
            const int j0 = wn * 16 + nt2 * 8 + fc;
            const int j1 = j0 + 4;
            const int n0 = nt2 * 2, n1 = nt2 * 2 + 1;   // epilogue-1 nt indices
            const float bh0 = __ldg(Uhb + j0), bh1 = __ldg(Uhb + j1);
            const float* a = ac2[mt][nt2];
            int r0 = mt * 16 + fr;
            stg[r0 * 132 + j0]       = (1.f - fs[mt][n0][0]) * tanhf(a[0] + bh0) + gs[mt][n0][0];
            stg[r0 * 132 + j1]       = (1.f - fs[mt][n1][0]) * tanhf(a[1] + bh1) + gs[mt][n1][0];
            stg[(r0 + 8) * 132 + j0] = (1.f - fs[mt][n0][1]) * tanhf(a[2] + bh0) + gs[mt][n0][1];
            stg[(r0 + 8) * 132 + j1] = (1.f - fs[mt][n1][1]) * tanhf(a[3] + bh1) + gs[mt][n1][1];
        }
    __syncthreads();

    // coalesced write-out
    for (int i = tid; i < 2048; i += 256) {
        int r = i >> 5, c = (i & 31) << 2;
        float4 v = *(const float4*)(stg + r * 132 + c);
        *(float4*)(h + ((size_t)batch * NN + node0 + r) * HD + c) = v;
    }
}

// --------------------------------------------------------------------------
// Init kernel: 64 leaf rows/CTA, 512 threads, 66KB smem, 2 CTAs/SM.
// --------------------------------------------------------------------------
__global__ __launch_bounds__(512, 2) void init_mma_k(
    const float* __restrict__ x, const float* __restrict__ Wb, float* __restrict__ h)
{
    extern __shared__ float sm[];
    float* sAf = sm;            // [rowblk(4)][kg(16)][lane(32)][4] = 8192 floats
    float* stg = sm + I_STG;    // 64 x 132 output staging

    const int tid = threadIdx.x, lane = tid & 31, wid = tid >> 5;
    const int batch = blockIdx.y;
    const int row0 = blockIdx.x * 64;   // leaf-local
    const float* xg = x + ((size_t)batch * NN + 16383 + row0) * HD;

    for (int i = tid; i < 2048; i += 512) {
        float4 v = ((const float4*)xg)[i];
        int r = i >> 5, c = (i & 31) << 2;
        int q = (((c & 7) >= 4) ? 2 : 0) + (((r & 15) >= 8) ? 1 : 0);
        float* dst = sAf + (((r >> 4) * 16 + (c >> 3)) * 32 + (r & 7) * 4) * 4 + q;
        dst[0]  = tf32r(v.x);
        dst[4]  = tf32r(v.y);
        dst[8]  = tf32r(v.z);
        dst[12] = tf32r(v.w);
    }
    __syncthreads();

    const int wm = wid & 1, wn = wid >> 1;
    const int wr = wm * 32;
    const int fr = lane >> 2, fc = lane & 3;

    float acc[2][4][4];
#pragma unroll
    for (int mt = 0; mt < 2; mt++)
#pragma unroll
        for (int nt = 0; nt < 4; nt++)
#pragma unroll
            for (int q = 0; q < 4; q++) acc[mt][nt][q] = 0.f;

#pragma unroll 4
    for (int kg = 0; kg < 16; kg++) {
        float4 av[2];
#pragma unroll
        for (int mt = 0; mt < 2; mt++)
            av[mt] = *(const float4*)(sAf + (((wm * 2 + mt) * 16 + kg) * 32 + lane) * 4);
#pragma unroll
        for (int nt = 0; nt < 4; nt++) {
            float2 bv = __ldg((const float2*)(d_W0 + ((kg * 32 + wn * 4 + nt) * 32 + lane) * 2));
#pragma unroll
            for (int mt = 0; mt < 2; mt++)
                mma8(acc[mt][nt], (const uint32_t*)&av[mt], (const uint32_t*)&bv);
        }
    }

#pragma unroll
    for (int mt = 0; mt < 2; mt++)
#pragma unroll
        for (int nt = 0; nt < 4; nt++) {
            const int j = wn * 16 + nt * 4 + fc;
            const float bA = __ldg(Wb + j), bB = __ldg(Wb + 128 + j);
#pragma unroll
            for (int half = 0; half < 2; half++) {
                int r = wr + mt * 16 + fr + half * 8;
                float f0 = sigm(acc[mt][nt][half * 2] + bA);
                float c0 = tanhf(acc[mt][nt][half * 2 + 1] + bB);
                stg[r * 132 + j] = (1.f - f0) * c0;
            }
        }
    __syncthreads();

    for (int i = tid; i < 2048; i += 512) {
        int r = i >> 5, c = (i & 31) << 2;
        float4 v = *(const float4*)(stg + r * 132 + c);
        *(float4*)(h + ((size_t)batch * NN + 16383 + row0 + r) * HD + c) = v;
    }
}

// --------------------------------------------------------------------------
// Small-level kernel (cnt < 64): SIMT GEMV, original weight layout.
// --------------------------------------------------------------------------
__global__ __launch_bounds__(256) void level_small_k(
    const float* __restrict__ Ufw, const float* __restrict__ Ufb,
    const float* __restrict__ Uhw, const float* __restrict__ Uhb,
    float* __restrict__ h, int start)
{
    __shared__ float hcs[256], gs[256], fs[256], red[256];
    const int tid = threadIdx.x, batch = blockIdx.y, node = start + blockIdx.x;

    hcs[tid] = h[((size_t)batch * NN + 2 * node + 1) * HD + tid];
    __syncthreads();

    float a0 = 0.f, a1 = 0.f, a2 = 0.f, a3 = 0.f;
#pragma unroll 8
    for (int k = 0; k < 256; k += 4) {
        a0 += hcs[k]     * Ufw[(size_t)(k)     * 256 + tid];
        a1 += hcs[k + 1] * Ufw[(size_t)(k + 1) * 256 + tid];
        a2 += hcs[k + 2] * Ufw[(size_t)(k + 2) * 256 + tid];
        a3 += hcs[k + 3] * Ufw[(size_t)(k + 3) * 256 + tid];
    }
    float f = sigm((a0 + a1) + (a2 + a3) + Ufb[tid]);
    fs[tid] = f;
    gs[tid] = f * hcs[tid];
    __syncthreads();

    const int j = tid & 127, k0 = (tid >> 7) * 128;
    float b0 = 0.f, b1 = 0.f, b2 = 0.f, b3 = 0.f;
#pragma unroll 8
    for (int k = 0; k < 128; k += 4) {
        b0 += gs[k0 + k]     * Uhw[(size_t)(k0 + k)     * 128 + j];
        b1 += gs[k0 + k + 1] * Uhw[(size_t)(k0 + k + 1) * 128 + j];
        b2 += gs[k0 + k + 2] * Uhw[(size_t)(k0 + k + 2) * 128 + j];
        b3 += gs[k0 + k + 3] * Uhw[(size_t)(k0 + k + 3) * 128 + j];
    }
    red[tid] = (b0 + b1) + (b2 + b3);
    __syncthreads();

    if (tid < 128) {
        float cand = tanhf(red[tid] + red[tid + 128] + Uhb[tid]);
        float out = (1.f - fs[tid] - fs[tid + 128]) * cand + gs[tid] + gs[tid + 128];
        h[((size_t)batch * NN + node) * HD + tid] = out;
    }
}

// --------------------------------------------------------------------------
extern "C" void kernel_launch(void* const* d_in, const int* in_sizes, int n_in,
                              void* d_out, int out_size)
{
    const float* x   = (const float*)d_in[0];
    const float* Ww  = (const float*)d_in[1];
    const float* Wb  = (const float*)d_in[2];
    const float* Ufw = (const float*)d_in[3];
    const float* Ufb = (const float*)d_in[4];
    const float* Uhw = (const float*)d_in[5];
    const float* Uhb = (const float*)d_in[6];
    float* h = (float*)d_out;

    cudaFuncSetAttribute(level_mma_k, cudaFuncAttributeMaxDynamicSharedMemorySize, SMEM_LVL);
    cudaFuncSetAttribute(init_mma_k,  cudaFuncAttributeMaxDynamicSharedMemorySize, SMEM_INI);

    prep_k<<<128, 256>>>(Ww, Ufw, Uhw);
    init_mma_k<<<dim3(256, NB), 512, SMEM_INI>>>(x, Wb, h);

    for (int l = 13; l >= 0; --l) {
        int start = (1 << l) - 1, cnt = 1 << l;
        if (cnt >= 64)
            level_mma_k<<<dim3(cnt / 64, NB), 256, SMEM_LVL>>>(Ufb, Uhb, h, start);
        else
            level_small_k<<<dim3(cnt, NB), 256>>>(Ufw, Ufb, Uhw, Uhb, h, start);
    }
}

// round 12
// speedup vs baseline: 1.0023x; 1.0023x over previous
#include <cuda_runtime.h>
#include <math.h>
#include <stdint.h>

#define NB 16
#define NN 32767
#define HD 128

// Fragment-packed tf32 weights in GLOBAL, layout [kg][nb][lane][2]:
//   elem[((kg*NBLK + nb)*32 + lane)*2 + p] = W[kg*8 + (lane&3) + 4p][col(nb,lane>>2)]
// d_Uf, d_W0 (NBLK=32): col = pairwise INTERLEAVE of (j, 128+j):  cI=2j / 2j+1
// d_Uh (NBLK=16):       col = within each 8-block, physical w holds logical (w>>1)+4(w&1)
__device__ float d_Uf[256 * 256];   // kg 0..31
__device__ float d_Uh[256 * 128];   // kg 0..31
__device__ float d_W0[128 * 256];   // kg 0..15

__device__ __forceinline__ float sigm(float v) { return 1.f / (1.f + expf(-v)); }
__device__ __forceinline__ float tf32r(float x) {
    float r; asm("cvt.rna.tf32.f32 %0, %1;" : "=f"(r) : "f"(x)); return r;
}
__device__ __forceinline__ void mma8(float* d, const uint32_t* a, const uint32_t* b) {
    asm volatile(
        "mma.sync.aligned.m16n8k8.row.col.f32.tf32.tf32.f32 "
        "{%0,%1,%2,%3}, {%4,%5,%6,%7}, {%8,%9}, {%0,%1,%2,%3};"
        : "+f"(d[0]), "+f"(d[1]), "+f"(d[2]), "+f"(d[3])
        : "r"(a[0]), "r"(a[1]), "r"(a[2]), "r"(a[3]), "r"(b[0]), "r"(b[1]));
}

// level smem (floats): sAf 16384 (A/g packed, 64 rows) | stg 8448 (out staging)
#define L_STG 16384
#define SMEM_LVL ((16384 + 8448) * 4)      // 99328 B -> 2 CTAs/SM @256thr
// init smem (floats): sAf 8192 | stg 8448
#define I_STG 8192
#define SMEM_INI ((8192 + 8448) * 4)       // 66560 B -> 2 CTAs/SM @512thr

// --------------------------------------------------------------------------
__global__ void prep_k(const float* __restrict__ Ww, const float* __restrict__ Ufw,
                       const float* __restrict__ Uhw)
{
    int i0 = blockIdx.x * blockDim.x + threadIdx.x, st = gridDim.x * blockDim.x;
    for (int idx = i0; idx < 131072; idx += st) {
        if (idx < 65536) {              // d_Uf (interleaved halves)
            int p = idx & 1, lane = (idx >> 1) & 31, nb = (idx >> 6) & 31, kg = idx >> 11;
            int k = kg * 8 + (lane & 3) + 4 * p;
            int cI = nb * 8 + (lane >> 2);
            int oc = (cI >> 1) + ((cI & 1) << 7);
            d_Uf[idx] = tf32r(Ufw[k * 256 + oc]);
        } else if (idx < 98304) {       // d_Uh (epilogue-matched permutation)
            int j = idx - 65536;
            int p = j & 1, lane = (j >> 1) & 31, nb = (j >> 6) & 15, kg = j >> 10;
            int k = kg * 8 + (lane & 3) + 4 * p;
            int w = lane >> 2;
            int n = nb * 8 + (w >> 1) + ((w & 1) << 2);
            d_Uh[j] = tf32r(Uhw[k * 128 + n]);
        } else {                        // d_W0 (interleaved halves)
            int j = idx - 98304;
            int p = j & 1, lane = (j >> 1) & 31, nb = (j >> 6) & 31, kg = j >> 11;
            int k = kg * 8 + (lane & 3) + 4 * p;
            int cI = nb * 8 + (lane >> 2);
            int oc = (cI >> 1) + ((cI & 1) << 7);
            d_W0[j] = tf32r(Ww[k * 256 + oc]);
        }
    }
}

// --------------------------------------------------------------------------
// Level kernel: 64 parents/CTA, 256 threads (8 warps; mt=4 M-tiles x 4 N-tiles).
// 2 CTAs/SM. fsum/gsum live in registers across both GEMMs.
// --------------------------------------------------------------------------
__global__ __launch_bounds__(256, 2) void level_mma_k(
    const float* __restrict__ Ufb, const float* __restrict__ Uhb,
    float* __restrict__ h, int start)
{
    extern __shared__ float sm[];
    float* sAf = sm;            // packed A/g fragments [rowblk(4)][kg(32)][lane(32)][4]
    float* stg = sm + L_STG;    // 64 x 132 output staging

    const int tid = threadIdx.x, lane = tid & 31, wn = tid >> 5;  // wn 0..7
    const int batch = blockIdx.y;
    const int node0 = start + blockIdx.x * 64;
    const float* hcg = h + ((size_t)batch * NN + 2 * node0 + 1) * HD;

    // load A = hc (64x256) into packed fragment layout, tf32-rounded
    for (int i = tid; i < 4096; i += 256) {
        float4 v = ((const float4*)hcg)[i];
        int r = i >> 6, c = (i & 63) << 2;
        int q = (((c & 7) >= 4) ? 2 : 0) + (((r & 15) >= 8) ? 1 : 0);
        float* dst = sAf + (((r >> 4) * 32 + (c >> 3)) * 32 + (r & 7) * 4) * 4 + q;
        dst[0]  = tf32r(v.x);
        dst[4]  = tf32r(v.y);
        dst[8]  = tf32r(v.z);
        dst[12] = tf32r(v.w);
    }
    __syncthreads();

    const int fr = lane >> 2, fc = lane & 3;

    // ---------------- phase 1: u = hc @ Uf (interleaved cols) ----------------
    float acc[4][4][4];
#pragma unroll
    for (int mt = 0; mt < 4; mt++)
#pragma unroll
        for (int nt = 0; nt < 4; nt++)
#pragma unroll
            for (int q = 0; q < 4; q++) acc[mt][nt][q] = 0.f;

#pragma unroll 2
    for (int kg = 0; kg < 32; kg++) {
        float4 av[4];
#pragma unroll
        for (int mt = 0; mt < 4; mt++)
            av[mt] = *(const float4*)(sAf + ((mt * 32 + kg) * 32 + lane) * 4);
#pragma unroll
        for (int nt = 0; nt < 4; nt++) {
            float2 bv = __ldg((const float2*)(d_Uf + ((kg * 32 + wn * 4 + nt) * 32 + lane) * 2));
#pragma unroll
            for (int mt = 0; mt < 4; mt++)
                mma8(acc[mt][nt], (const uint32_t*)&av[mt], (const uint32_t*)&bv);
        }
    }
    __syncthreads();   // phase-1 A reads complete before g overwrite

    // ---------------- epilogue 1: f, g, fsum/gsum (registers) ----------------
    float fs[4][4][2], gs[4][4][2];
#pragma unroll
    for (int nt = 0; nt < 4; nt++) {
        const int j = wn * 16 + nt * 4 + fc;
        const float bfA = __ldg(Ufb + j), bfB = __ldg(Ufb + 128 + j);
        const int kgA = j >> 3, khalf2 = ((j & 7) >= 4) ? 2 : 0;
#pragma unroll
        for (int mt = 0; mt < 4; mt++)
#pragma unroll
            for (int half = 0; half < 2; half++) {
                int r = mt * 16 + fr + half * 8;
                float fA = sigm(acc[mt][nt][half * 2] + bfA);
                float fB = sigm(acc[mt][nt][half * 2 + 1] + bfB);
                float hA = __ldg(hcg + r * 256 + j);
                float hB = __ldg(hcg + r * 256 + 128 + j);
                float gA = fA * hA, gB = fB * hB;
                int q = khalf2 + half;
                int base = (mt * 32) * 128 + lane * 4 + q;
                sAf[base + kgA * 128]        = tf32r(gA);
                sAf[base + (kgA + 16) * 128] = tf32r(gB);
                fs[mt][nt][half] = fA + fB;
                gs[mt][nt][half] = gA + gB;   // exact fp32
            }
    }
    __syncthreads();   // g visible to all warps

    // ---------------- phase 2: v = g @ Uh (permuted cols) ----------------
    float ac2[4][2][4];
#pragma unroll
    for (int mt = 0; mt < 4; mt++)
#pragma unroll
        for (int nt = 0; nt < 2; nt++)
#pragma unroll
            for (int q = 0; q < 4; q++) ac2[mt][nt][q] = 0.f;

#pragma unroll 2
    for (int kg = 0; kg < 32; kg++) {
        float4 av[4];
#pragma unroll
        for (int mt = 0; mt < 4; mt++)
            av[mt] = *(const float4*)(sAf + ((mt * 32 + kg) * 32 + lane) * 4);
#pragma unroll
        for (int nt = 0; nt < 2; nt++) {
            float2 bv = __ldg((const float2*)(d_Uh + ((kg * 16 + wn * 2 + nt) * 32 + lane) * 2));
#pragma unroll
            for (int mt = 0; mt < 4; mt++)
                mma8(ac2[mt][nt], (const uint32_t*)&av[mt], (const uint32_t*)&bv);
        }
    }

    // ---------------- epilogue 2 (ownership matches epilogue 1) -------------
    // ac2[mt][nt2] pair (d0,d1) = logical cols (j0, j0+4), j0 = wn*16+nt2*8+fc.
#pragma unroll
    for (int mt = 0; mt < 4; mt++)
#pragma unroll
        for (int nt2 = 0; nt2 < 2; nt2++) {
            const int j0 = wn * 16 + nt2 * 8 + fc;
            const int j1 = j0 + 4;
            const int n0 = nt2 * 2, n1 = nt2 * 2 + 1;   // epilogue-1 nt indices
            const float bh0 = __ldg(Uhb + j0), bh1 = __ldg(Uhb + j1);
            const float* a = ac2[mt][nt2];
            int r0 = mt * 16 + fr;
            stg[r0 * 132 + j0]       = (1.f - fs[mt][n0][0]) * tanhf(a[0] + bh0) + gs[mt][n0][0];
            stg[r0 * 132 + j1]       = (1.f - fs[mt][n1][0]) * tanhf(a[1] + bh1) + gs[mt][n1][0];
            stg[(r0 + 8) * 132 + j0] = (1.f - fs[mt][n0][1]) * tanhf(a[2] + bh0) + gs[mt][n0][1];
            stg[(r0 + 8) * 132 + j1] = (1.f - fs[mt][n1][1]) * tanhf(a[3] + bh1) + gs[mt][n1][1];
        }
    __syncthreads();

    // coalesced write-out
    for (int i = tid; i < 2048; i += 256) {
        int r = i >> 5, c = (i & 31) << 2;
        float4 v = *(const float4*)(stg + r * 132 + c);
        *(float4*)(h + ((size_t)batch * NN + node0 + r) * HD + c) = v;
    }
}

// --------------------------------------------------------------------------
// Init kernel: 64 leaf rows/CTA, 512 threads, 66KB smem, 2 CTAs/SM.
// --------------------------------------------------------------------------
__global__ __launch_bounds__(512, 2) void init_mma_k(
    const float* __restrict__ x, const float* __restrict__ Wb, float* __restrict__ h)
{
    extern __shared__ float sm[];
    float* sAf = sm;            // [rowblk(4)][kg(16)][lane(32)][4] = 8192 floats
    float* stg = sm + I_STG;    // 64 x 132 output staging

    const int tid = threadIdx.x, lane = tid & 31, wid = tid >> 5;
    const int batch = blockIdx.y;
    const int row0 = blockIdx.x * 64;   // leaf-local
    const float* xg = x + ((size_t)batch * NN + 16383 + row0) * HD;

    for (int i = tid; i < 2048; i += 512) {
        float4 v = ((const float4*)xg)[i];
        int r = i >> 5, c = (i & 31) << 2;
        int q = (((c & 7) >= 4) ? 2 : 0) + (((r & 15) >= 8) ? 1 : 0);
        float* dst = sAf + (((r >> 4) * 16 + (c >> 3)) * 32 + (r & 7) * 4) * 4 + q;
        dst[0]  = tf32r(v.x);
        dst[4]  = tf32r(v.y);
        dst[8]  = tf32r(v.z);
        dst[12] = tf32r(v.w);
    }
    __syncthreads();

    const int wm = wid & 1, wn = wid >> 1;
    const int wr = wm * 32;
    const int fr = lane >> 2, fc = lane & 3;

    float acc[2][4][4];
#pragma unroll
    for (int mt = 0; mt < 2; mt++)
#pragma unroll
        for (int nt = 0; nt < 4; nt++)
#pragma unroll
            for (int q = 0; q < 4; q++) acc[mt][nt][q] = 0.f;

#pragma unroll 4
    for (int kg = 0; kg < 16; kg++) {
        float4 av[2];
#pragma unroll
        for (int mt = 0; mt < 2; mt++)
            av[mt] = *(const float4*)(sAf + (((wm * 2 + mt) * 16 + kg) * 32 + lane) * 4);
#pragma unroll
        for (int nt = 0; nt < 4; nt++) {
            float2 bv = __ldg((const float2*)(d_W0 + ((kg * 32 + wn * 4 + nt) * 32 + lane) * 2));
#pragma unroll
            for (int mt = 0; mt < 2; mt++)
                mma8(acc[mt][nt], (const uint32_t*)&av[mt], (const uint32_t*)&bv);
        }
    }

#pragma unroll
    for (int mt = 0; mt < 2; mt++)
#pragma unroll
        for (int nt = 0; nt < 4; nt++) {
            const int j = wn * 16 + nt * 4 + fc;
            const float bA = __ldg(Wb + j), bB = __ldg(Wb + 128 + j);
#pragma unroll
            for (int half = 0; half < 2; half++) {
                int r = wr + mt * 16 + fr + half * 8;
                float f0 = sigm(acc[mt][nt][half * 2] + bA);
                float c0 = tanhf(acc[mt][nt][half * 2 + 1] + bB);
                stg[r * 132 + j] = (1.f - f0) * c0;
            }
        }
    __syncthreads();

    for (int i = tid; i < 2048; i += 512) {
        int r = i >> 5, c = (i & 31) << 2;
        float4 v = *(const float4*)(stg + r * 132 + c);
        *(float4*)(h + ((size_t)batch * NN + 16383 + row0 + r) * HD + c) = v;
    }
}

// --------------------------------------------------------------------------
// Small-level kernel (cnt < 64): SIMT GEMV, original weight layout.
// --------------------------------------------------------------------------
__global__ __launch_bounds__(256) void level_small_k(
    const float* __restrict__ Ufw, const float* __restrict__ Ufb,
    const float* __restrict__ Uhw, const float* __restrict__ Uhb,
    float* __restrict__ h, int start)
{
    __shared__ float hcs[256], gs[256], fs[256], red[256];
    const int tid = threadIdx.x, batch = blockIdx.y, node = start + blockIdx.x;

    hcs[tid] = h[((size_t)batch * NN + 2 * node + 1) * HD + tid];
    __syncthreads();

    float a0 = 0.f, a1 = 0.f, a2 = 0.f, a3 = 0.f;
#pragma unroll 8
    for (int k = 0; k < 256; k += 4) {
        a0 += hcs[k]     * Ufw[(size_t)(k)     * 256 + tid];
        a1 += hcs[k + 1] * Ufw[(size_t)(k + 1) * 256 + tid];
        a2 += hcs[k + 2] * Ufw[(size_t)(k + 2) * 256 + tid];
        a3 += hcs[k + 3] * Ufw[(size_t)(k + 3) * 256 + tid];
    }
    float f = sigm((a0 + a1) + (a2 + a3) + Ufb[tid]);
    fs[tid] = f;
    gs[tid] = f * hcs[tid];
    __syncthreads();

    const int j = tid & 127, k0 = (tid >> 7) * 128;
    float b0 = 0.f, b1 = 0.f, b2 = 0.f, b3 = 0.f;
#pragma unroll 8
    for (int k = 0; k < 128; k += 4) {
        b0 += gs[k0 + k]     * Uhw[(size_t)(k0 + k)     * 128 + j];
        b1 += gs[k0 + k + 1] * Uhw[(size_t)(k0 + k + 1) * 128 + j];
        b2 += gs[k0 + k + 2] * Uhw[(size_t)(k0 + k + 2) * 128 + j];
        b3 += gs[k0 + k + 3] * Uhw[(size_t)(k0 + k + 3) * 128 + j];
    }
    red[tid] = (b0 + b1) + (b2 + b3);
    __syncthreads();

    if (tid < 128) {
        float cand = tanhf(red[tid] + red[tid + 128] + Uhb[tid]);
        float out = (1.f - fs[tid] - fs[tid + 128]) * cand + gs[tid] + gs[tid + 128];
        h[((size_t)batch * NN + node) * HD + tid] = out;
    }
}

// --------------------------------------------------------------------------
extern "C" void kernel_launch(void* const* d_in, const int* in_sizes, int n_in,
                              void* d_out, int out_size)
{
    const float* x   = (const float*)d_in[0];
    const float* Ww  = (const float*)d_in[1];
    const float* Wb  = (const float*)d_in[2];
    const float* Ufw = (const float*)d_in[3];
    const float* Ufb = (const float*)d_in[4];
    const float* Uhw = (const float*)d_in[5];
    const float* Uhb = (const float*)d_in[6];
    float* h = (float*)d_out;

    cudaFuncSetAttribute(level_mma_k, cudaFuncAttributeMaxDynamicSharedMemorySize, SMEM_LVL);
    cudaFuncSetAttribute(init_mma_k,  cudaFuncAttributeMaxDynamicSharedMemorySize, SMEM_INI);

    prep_k<<<128, 256>>>(Ww, Ufw, Uhw);
    init_mma_k<<<dim3(256, NB), 512, SMEM_INI>>>(x, Wb, h);

    for (int l = 13; l >= 0; --l) {
        int start = (1 << l) - 1, cnt = 1 << l;
        if (cnt >= 64)
            level_mma_k<<<dim3(cnt / 64, NB), 256, SMEM_LVL>>>(Ufb, Uhb, h, start);
        else
            level_small_k<<<dim3(cnt, NB), 256>>>(Ufw, Ufb, Uhw, Uhb, h, start);
    }
}

// round 13
// speedup vs baseline: 1.0191x; 1.0167x over previous
#include <cuda_runtime.h>
#include <math.h>
#include <stdint.h>

#define NB 16
#define NN 32767
#define HD 128

// Fragment-packed tf32 weights in GLOBAL, layout [kg][nb][lane][2]:
//   elem[((kg*NBLK + nb)*32 + lane)*2 + p] = W[kg*8 + (lane&3) + 4p][col(nb,lane>>2)]
// d_Uf, d_W0 (NBLK=32): col = pairwise INTERLEAVE of (j, 128+j):  cI=2j / 2j+1
// d_Uh (NBLK=16):       col = within each 8-block, physical w holds logical (w>>1)+4(w&1)
__device__ float d_Uf[256 * 256];   // kg 0..31
__device__ float d_Uh[256 * 128];   // kg 0..31
__device__ float d_W0[128 * 256];   // kg 0..15

__device__ __forceinline__ float sigm(float v) { return 1.f / (1.f + expf(-v)); }
__device__ __forceinline__ float tf32r(float x) {
    float r; asm("cvt.rna.tf32.f32 %0, %1;" : "=f"(r) : "f"(x)); return r;
}
__device__ __forceinline__ void mma8(float* d, const uint32_t* a, const uint32_t* b) {
    asm volatile(
        "mma.sync.aligned.m16n8k8.row.col.f32.tf32.tf32.f32 "
        "{%0,%1,%2,%3}, {%4,%5,%6,%7}, {%8,%9}, {%0,%1,%2,%3};"
        : "+f"(d[0]), "+f"(d[1]), "+f"(d[2]), "+f"(d[3])
        : "r"(a[0]), "r"(a[1]), "r"(a[2]), "r"(a[3]), "r"(b[0]), "r"(b[1]));
}

// level smem (floats): sAf 16384 (A/g packed; recycled as output staging) | sFS 8448 (fsum)
#define L_FS 16384
#define SMEM_LVL ((16384 + 8448) * 4)      // 99328 B -> 2 CTAs/SM @256thr
// init smem (floats): sAf 8192 | stg 8448
#define I_STG 8192
#define SMEM_INI ((8192 + 8448) * 4)       // 66560 B -> 2 CTAs/SM @512thr

// --------------------------------------------------------------------------
__global__ void prep_k(const float* __restrict__ Ww, const float* __restrict__ Ufw,
                       const float* __restrict__ Uhw)
{
    int i0 = blockIdx.x * blockDim.x + threadIdx.x, st = gridDim.x * blockDim.x;
    for (int idx = i0; idx < 131072; idx += st) {
        if (idx < 65536) {              // d_Uf (interleaved halves)
            int p = idx & 1, lane = (idx >> 1) & 31, nb = (idx >> 6) & 31, kg = idx >> 11;
            int k = kg * 8 + (lane & 3) + 4 * p;
            int cI = nb * 8 + (lane >> 2);
            int oc = (cI >> 1) + ((cI & 1) << 7);
            d_Uf[idx] = tf32r(Ufw[k * 256 + oc]);
        } else if (idx < 98304) {       // d_Uh (epilogue-matched permutation)
            int j = idx - 65536;
            int p = j & 1, lane = (j >> 1) & 31, nb = (j >> 6) & 15, kg = j >> 10;
            int k = kg * 8 + (lane & 3) + 4 * p;
            int w = lane >> 2;
            int n = nb * 8 + (w >> 1) + ((w & 1) << 2);
            d_Uh[j] = tf32r(Uhw[k * 128 + n]);
        } else {                        // d_W0 (interleaved halves)
            int j = idx - 98304;
            int p = j & 1, lane = (j >> 1) & 31, nb = (j >> 6) & 31, kg = j >> 11;
            int k = kg * 8 + (lane & 3) + 4 * p;
            int cI = nb * 8 + (lane >> 2);
            int oc = (cI >> 1) + ((cI & 1) << 7);
            d_W0[j] = tf32r(Ww[k * 256 + oc]);
        }
    }
}

// --------------------------------------------------------------------------
// Level kernel: 64 parents/CTA, 256 threads (8 warps; mt=4 x 4 N-tiles).
// 2 CTAs/SM. gsum in registers, fsum in smem, output staged via recycled sAf.
// --------------------------------------------------------------------------
__global__ __launch_bounds__(256, 2) void level_mma_k(
    const float* __restrict__ Ufb, const float* __restrict__ Uhb,
    float* __restrict__ h, int start)
{
    extern __shared__ float sm[];
    float* sAf = sm;            // packed A/g fragments [rowblk(4)][kg(32)][lane(32)][4]
    float* sFS = sm + L_FS;     // 64 x 132 fsum

    const int tid = threadIdx.x, lane = tid & 31, wn = tid >> 5;  // wn 0..7
    const int batch = blockIdx.y;
    const int node0 = start + blockIdx.x * 64;
    const float* hcg = h + ((size_t)batch * NN + 2 * node0 + 1) * HD;

    // load A = hc (64x256) into packed fragment layout, tf32-rounded
    for (int i = tid; i < 4096; i += 256) {
        float4 v = ((const float4*)hcg)[i];
        int r = i >> 6, c = (i & 63) << 2;
        int q = (((c & 7) >= 4) ? 2 : 0) + (((r & 15) >= 8) ? 1 : 0);
        float* dst = sAf + (((r >> 4) * 32 + (c >> 3)) * 32 + (r & 7) * 4) * 4 + q;
        dst[0]  = tf32r(v.x);
        dst[4]  = tf32r(v.y);
        dst[8]  = tf32r(v.z);
        dst[12] = tf32r(v.w);
    }
    __syncthreads();

    const int fr = lane >> 2, fc = lane & 3;

    // ---------------- phase 1: u = hc @ Uf (interleaved cols) ----------------
    float acc[4][4][4];
#pragma unroll
    for (int mt = 0; mt < 4; mt++)
#pragma unroll
        for (int nt = 0; nt < 4; nt++)
#pragma unroll
            for (int q = 0; q < 4; q++) acc[mt][nt][q] = 0.f;

#pragma unroll 2
    for (int kg = 0; kg < 32; kg++) {
        float4 av[4];
#pragma unroll
        for (int mt = 0; mt < 4; mt++)
            av[mt] = *(const float4*)(sAf + ((mt * 32 + kg) * 32 + lane) * 4);
#pragma unroll
        for (int nt = 0; nt < 4; nt++) {
            float2 bv = __ldg((const float2*)(d_Uf + ((kg * 32 + wn * 4 + nt) * 32 + lane) * 2));
#pragma unroll
            for (int mt = 0; mt < 4; mt++)
                mma8(acc[mt][nt], (const uint32_t*)&av[mt], (const uint32_t*)&bv);
        }
    }
    __syncthreads();   // phase-1 A reads complete before g overwrite

    // ------- epilogue 1: f, g; fsum -> smem, gsum -> registers --------------
    float gs[4][4][2];
#pragma unroll
    for (int nt = 0; nt < 4; nt++) {
        const int j = wn * 16 + nt * 4 + fc;
        const float bfA = __ldg(Ufb + j), bfB = __ldg(Ufb + 128 + j);
        const int kgA = j >> 3, khalf2 = ((j & 7) >= 4) ? 2 : 0;
#pragma unroll
        for (int mt = 0; mt < 4; mt++)
#pragma unroll
            for (int half = 0; half < 2; half++) {
                int r = mt * 16 + fr + half * 8;
                float fA = sigm(acc[mt][nt][half * 2] + bfA);
                float fB = sigm(acc[mt][nt][half * 2 + 1] + bfB);
                float hA = __ldg(hcg + r * 256 + j);
                float hB = __ldg(hcg + r * 256 + 128 + j);
                float gA = fA * hA, gB = fB * hB;
                int q = khalf2 + half;
                int base = (mt * 32) * 128 + lane * 4 + q;
                sAf[base + kgA * 128]        = tf32r(gA);
                sAf[base + (kgA + 16) * 128] = tf32r(gB);
                sFS[r * 132 + j]  = fA + fB;     // fsum -> smem
                gs[mt][nt][half] = gA + gB;      // gsum -> regs (exact fp32)
            }
    }
    __syncthreads();   // g / fsum visible to all warps

    // ---------------- phase 2: v = g @ Uh (permuted cols) ----------------
    float ac2[4][2][4];
#pragma unroll
    for (int mt = 0; mt < 4; mt++)
#pragma unroll
        for (int nt = 0; nt < 2; nt++)
#pragma unroll
            for (int q = 0; q < 4; q++) ac2[mt][nt][q] = 0.f;

#pragma unroll 2
    for (int kg = 0; kg < 32; kg++) {
        float4 av[4];
#pragma unroll
        for (int mt = 0; mt < 4; mt++)
            av[mt] = *(const float4*)(sAf + ((mt * 32 + kg) * 32 + lane) * 4);
#pragma unroll
        for (int nt = 0; nt < 2; nt++) {
            float2 bv = __ldg((const float2*)(d_Uh + ((kg * 16 + wn * 2 + nt) * 32 + lane) * 2));
#pragma unroll
            for (int mt = 0; mt < 4; mt++)
                mma8(ac2[mt][nt], (const uint32_t*)&av[mt], (const uint32_t*)&bv);
        }
    }
    __syncthreads();   // all warps done reading sAf -> safe to recycle as staging

    // ------- epilogue 2 (ownership matches epilogue 1; stage into sAf) ------
    float* stg = sAf;   // 64 x 132 staging, recycled
#pragma unroll
    for (int mt = 0; mt < 4; mt++)
#pragma unroll
        for (int nt2 = 0; nt2 < 2; nt2++) {
            const int j0 = wn * 16 + nt2 * 8 + fc;
            const int j1 = j0 + 4;
            const int n0 = nt2 * 2, n1 = nt2 * 2 + 1;   // epilogue-1 nt indices
            const float bh0 = __ldg(Uhb + j0), bh1 = __ldg(Uhb + j1);
            const float* a = ac2[mt][nt2];
            int r0 = mt * 16 + fr;
            int r1 = r0 + 8;
            stg[r0 * 132 + j0] = (1.f - sFS[r0 * 132 + j0]) * tanhf(a[0] + bh0) + gs[mt][n0][0];
            stg[r0 * 132 + j1] = (1.f - sFS[r0 * 132 + j1]) * tanhf(a[1] + bh1) + gs[mt][n1][0];
            stg[r1 * 132 + j0] = (1.f - sFS[r1 * 132 + j0]) * tanhf(a[2] + bh0) + gs[mt][n0][1];
            stg[r1 * 132 + j1] = (1.f - sFS[r1 * 132 + j1]) * tanhf(a[3] + bh1) + gs[mt][n1][1];
        }
    __syncthreads();

    // coalesced write-out
    for (int i = tid; i < 2048; i += 256) {
        int r = i >> 5, c = (i & 31) << 2;
        float4 v = *(const float4*)(stg + r * 132 + c);
        *(float4*)(h + ((size_t)batch * NN + node0 + r) * HD + c) = v;
    }
}

// --------------------------------------------------------------------------
// Init kernel: 64 leaf rows/CTA, 512 threads, 66KB smem, 2 CTAs/SM.
// --------------------------------------------------------------------------
__global__ __launch_bounds__(512, 2) void init_mma_k(
    const float* __restrict__ x, const float* __restrict__ Wb, float* __restrict__ h)
{
    extern __shared__ float sm[];
    float* sAf = sm;            // [rowblk(4)][kg(16)][lane(32)][4] = 8192 floats
    float* stg = sm + I_STG;    // 64 x 132 output staging

    const int tid = threadIdx.x, lane = tid & 31, wid = tid >> 5;
    const int batch = blockIdx.y;
    const int row0 = blockIdx.x * 64;   // leaf-local
    const float* xg = x + ((size_t)batch * NN + 16383 + row0) * HD;

    for (int i = tid; i < 2048; i += 512) {
        float4 v = ((const float4*)xg)[i];
        int r = i >> 5, c = (i & 31) << 2;
        int q = (((c & 7) >= 4) ? 2 : 0) + (((r & 15) >= 8) ? 1 : 0);
        float* dst = sAf + (((r >> 4) * 16 + (c >> 3)) * 32 + (r & 7) * 4) * 4 + q;
        dst[0]  = tf32r(v.x);
        dst[4]  = tf32r(v.y);
        dst[8]  = tf32r(v.z);
        dst[12] = tf32r(v.w);
    }
    __syncthreads();

    const int wm = wid & 1, wn = wid >> 1;
    const int wr = wm * 32;
    const int fr = lane >> 2, fc = lane & 3;

    float acc[2][4][4];
#pragma unroll
    for (int mt = 0; mt < 2; mt++)
#pragma unroll
        for (int nt = 0; nt < 4; nt++)
#pragma unroll
            for (int q = 0; q < 4; q++) acc[mt][nt][q] = 0.f;

#pragma unroll 4
    for (int kg = 0; kg < 16; kg++) {
        float4 av[2];
#pragma unroll
        for (int mt = 0; mt < 2; mt++)
            av[mt] = *(const float4*)(sAf + (((wm * 2 + mt) * 16 + kg) * 32 + lane) * 4);
#pragma unroll
        for (int nt = 0; nt < 4; nt++) {
            float2 bv = __ldg((const float2*)(d_W0 + ((kg * 32 + wn * 4 + nt) * 32 + lane) * 2));
#pragma unroll
            for (int mt = 0; mt < 2; mt++)
                mma8(acc[mt][nt], (const uint32_t*)&av[mt], (const uint32_t*)&bv);
        }
    }

#pragma unroll
    for (int mt = 0; mt < 2; mt++)
#pragma unroll
        for (int nt = 0; nt < 4; nt++) {
            const int j = wn * 16 + nt * 4 + fc;
            const float bA = __ldg(Wb + j), bB = __ldg(Wb + 128 + j);
#pragma unroll
            for (int half = 0; half < 2; half++) {
                int r = wr + mt * 16 + fr + half * 8;
                float f0 = sigm(acc[mt][nt][half * 2] + bA);
                float c0 = tanhf(acc[mt][nt][half * 2 + 1] + bB);
                stg[r * 132 + j] = (1.f - f0) * c0;
            }
        }
    __syncthreads();

    for (int i = tid; i < 2048; i += 512) {
        int r = i >> 5, c = (i & 31) << 2;
        float4 v = *(const float4*)(stg + r * 132 + c);
        *(float4*)(h + ((size_t)batch * NN + 16383 + row0 + r) * HD + c) = v;
    }
}

// --------------------------------------------------------------------------
// Small-level kernel (cnt < 64): SIMT GEMV, original weight layout.
// --------------------------------------------------------------------------
__global__ __launch_bounds__(256) void level_small_k(
    const float* __restrict__ Ufw, const float* __restrict__ Ufb,
    const float* __restrict__ Uhw, const float* __restrict__ Uhb,
    float* __restrict__ h, int start)
{
    __shared__ float hcs[256], gs[256], fs[256], red[256];
    const int tid = threadIdx.x, batch = blockIdx.y, node = start + blockIdx.x;

    hcs[tid] = h[((size_t)batch * NN + 2 * node + 1) * HD + tid];
    __syncthreads();

    float a0 = 0.f, a1 = 0.f, a2 = 0.f, a3 = 0.f;
#pragma unroll 8
    for (int k = 0; k < 256; k += 4) {
        a0 += hcs[k]     * Ufw[(size_t)(k)     * 256 + tid];
        a1 += hcs[k + 1] * Ufw[(size_t)(k + 1) * 256 + tid];
        a2 += hcs[k + 2] * Ufw[(size_t)(k + 2) * 256 + tid];
        a3 += hcs[k + 3] * Ufw[(size_t)(k + 3) * 256 + tid];
    }
    float f = sigm((a0 + a1) + (a2 + a3) + Ufb[tid]);
    fs[tid] = f;
    gs[tid] = f * hcs[tid];
    __syncthreads();

    const int j = tid & 127, k0 = (tid >> 7) * 128;
    float b0 = 0.f, b1 = 0.f, b2 = 0.f, b3 = 0.f;
#pragma unroll 8
    for (int k = 0; k < 128; k += 4) {
        b0 += gs[k0 + k]     * Uhw[(size_t)(k0 + k)     * 128 + j];
        b1 += gs[k0 + k + 1] * Uhw[(size_t)(k0 + k + 1) * 128 + j];
        b2 += gs[k0 + k + 2] * Uhw[(size_t)(k0 + k + 2) * 128 + j];
        b3 += gs[k0 + k + 3] * Uhw[(size_t)(k0 + k + 3) * 128 + j];
    }
    red[tid] = (b0 + b1) + (b2 + b3);
    __syncthreads();

    if (tid < 128) {
        float cand = tanhf(red[tid] + red[tid + 128] + Uhb[tid]);
        float out = (1.f - fs[tid] - fs[tid + 128]) * cand + gs[tid] + gs[tid + 128];
        h[((size_t)batch * NN + node) * HD + tid] = out;
    }
}

// --------------------------------------------------------------------------
extern "C" void kernel_launch(void* const* d_in, const int* in_sizes, int n_in,
                              void* d_out, int out_size)
{
    const float* x   = (const float*)d_in[0];
    const float* Ww  = (const float*)d_in[1];
    const float* Wb  = (const float*)d_in[2];
    const float* Ufw = (const float*)d_in[3];
    const float* Ufb = (const float*)d_in[4];
    const float* Uhw = (const float*)d_in[5];
    const float* Uhb = (const float*)d_in[6];
    float* h = (float*)d_out;

    cudaFuncSetAttribute(level_mma_k, cudaFuncAttributeMaxDynamicSharedMemorySize, SMEM_LVL);
    cudaFuncSetAttribute(init_mma_k,  cudaFuncAttributeMaxDynamicSharedMemorySize, SMEM_INI);

    prep_k<<<128, 256>>>(Ww, Ufw, Uhw);
    init_mma_k<<<dim3(256, NB), 512, SMEM_INI>>>(x, Wb, h);

    for (int l = 13; l >= 0; --l) {
        int start = (1 << l) - 1, cnt = 1 << l;
        if (cnt >= 64)
            level_mma_k<<<dim3(cnt / 64, NB), 256, SMEM_LVL>>>(Ufb, Uhb, h, start);
        else
            level_small_k<<<dim3(cnt, NB), 256>>>(Ufw, Ufb, Uhw, Uhb, h, start);
    }
}

// round 15
// speedup vs baseline: 1.0491x; 1.0295x over previous
#include <cuda_runtime.h>
#include <math.h>
#include <stdint.h>

#define NB 16
#define NN 32767
#define HD 128

// Fragment-packed tf32 weights in GLOBAL, layout [kg][nb][lane][2]:
//   elem[((kg*NBLK + nb)*32 + lane)*2 + p] = W[kg*8 + (lane&3) + 4p][col(nb,lane>>2)]
// d_Uf, d_W0 (NBLK=32): col = pairwise INTERLEAVE of (j, 128+j): cI=2j <-> j, 2j+1 <-> 128+j
// d_Uh (NBLK=16):       plain col = nb*8 + (lane>>2)
__device__ float d_Uf[256 * 256];   // kg 0..31
__device__ float d_Uh[256 * 128];   // kg 0..31
__device__ float d_W0[128 * 256];   // kg 0..15

__device__ __forceinline__ float sigm(float v) { return 1.f / (1.f + expf(-v)); }
__device__ __forceinline__ float tf32r(float x) {
    float r; asm("cvt.rna.tf32.f32 %0, %1;" : "=f"(r) : "f"(x)); return r;
}
__device__ __forceinline__ void mma8(float* d, const uint32_t* a, const uint32_t* b) {
    asm volatile(
        "mma.sync.aligned.m16n8k8.row.col.f32.tf32.tf32.f32 "
        "{%0,%1,%2,%3}, {%4,%5,%6,%7}, {%8,%9}, {%0,%1,%2,%3};"
        : "+f"(d[0]), "+f"(d[1]), "+f"(d[2]), "+f"(d[3])
        : "r"(a[0]), "r"(a[1]), "r"(a[2]), "r"(a[3]), "r"(b[0]), "r"(b[1]));
}

#define FS 260
// level smem (floats): sAf 8192 | sFG 8320   (32-row tile)
#define L_FG 8192
#define SMEM_LVL ((8192 + 8320) * 4)       // 66048 B -> 2 CTAs/SM @256thr
// init smem (floats): sAf 8192 | stg 8448
#define I_STG 8192
#define SMEM_INI ((8192 + 8448) * 4)       // 66560 B -> 2 CTAs/SM @512thr

// --------------------------------------------------------------------------
__global__ void prep_k(const float* __restrict__ Ww, const float* __restrict__ Ufw,
                       const float* __restrict__ Uhw)
{
    int i0 = blockIdx.x * blockDim.x + threadIdx.x, st = gridDim.x * blockDim.x;
    for (int idx = i0; idx < 131072; idx += st) {
        if (idx < 65536) {              // d_Uf
            int p = idx & 1, lane = (idx >> 1) & 31, nb = (idx >> 6) & 31, kg = idx >> 11;
            int k = kg * 8 + (lane & 3) + 4 * p;
            int cI = nb * 8 + (lane >> 2);
            int oc = (cI >> 1) + ((cI & 1) << 7);
            d_Uf[idx] = tf32r(Ufw[k * 256 + oc]);
        } else if (idx < 98304) {       // d_Uh
            int j = idx - 65536;
            int p = j & 1, lane = (j >> 1) & 31, nb = (j >> 6) & 15, kg = j >> 10;
            int k = kg * 8 + (lane & 3) + 4 * p;
            int n = nb * 8 + (lane >> 2);
            d_Uh[j] = tf32r(Uhw[k * 128 + n]);
        } else {                        // d_W0
            int j = idx - 98304;
            int p = j & 1, lane = (j >> 1) & 31, nb = (j >> 6) & 31, kg = j >> 11;
            int k = kg * 8 + (lane & 3) + 4 * p;
            int cI = nb * 8 + (lane >> 2);
            int oc = (cI >> 1) + ((cI & 1) << 7);
            d_W0[j] = tf32r(Ww[k * 256 + oc]);
        }
    }
}

// --------------------------------------------------------------------------
// Shared 32-row MGU tile body (R9-measured-best config): 256 threads, 8 warps
// all in N, mt=2. Stores guarded by row < cnt (cnt=32 for full tiles).
// --------------------------------------------------------------------------
__device__ __forceinline__ void mgu_tile32(
    float* sAf, float* sFG, const float* hcg, float* outbase, int cnt,
    const float* __restrict__ Ufb, const float* __restrict__ Uhb,
    int tid, int lane, int wn)
{
    // load A = hc (32x256) into packed fragment layout, tf32-rounded
    for (int i = tid; i < 2048; i += 256) {
        float4 v = ((const float4*)hcg)[i];
        int r = i >> 6, c = (i & 63) << 2;
        int q = (((c & 7) >= 4) ? 2 : 0) + (((r & 15) >= 8) ? 1 : 0);
        float* dst = sAf + (((r >> 4) * 32 + (c >> 3)) * 32 + (r & 7) * 4) * 4 + q;
        dst[0]  = tf32r(v.x);
        dst[4]  = tf32r(v.y);
        dst[8]  = tf32r(v.z);
        dst[12] = tf32r(v.w);
    }
    __syncthreads();

    const int fr = lane >> 2, fc = lane & 3;

    // phase 1: u = hc @ Uf (interleaved cols)
    float acc[2][4][4];
#pragma unroll
    for (int mt = 0; mt < 2; mt++)
#pragma unroll
        for (int nt = 0; nt < 4; nt++)
#pragma unroll
            for (int q = 0; q < 4; q++) acc[mt][nt][q] = 0.f;

#pragma unroll 4
    for (int kg = 0; kg < 32; kg++) {
        float4 av[2];
#pragma unroll
        for (int mt = 0; mt < 2; mt++)
            av[mt] = *(const float4*)(sAf + ((mt * 32 + kg) * 32 + lane) * 4);
#pragma unroll
        for (int nt = 0; nt < 4; nt++) {
            float2 bv = __ldg((const float2*)(d_Uf + ((kg * 32 + wn * 4 + nt) * 32 + lane) * 2));
#pragma unroll
            for (int mt = 0; mt < 2; mt++)
                mma8(acc[mt][nt], (const uint32_t*)&av[mt], (const uint32_t*)&bv);
        }
    }
    __syncthreads();   // phase-1 A reads complete before g overwrite

    // epilogue 1
#pragma unroll
    for (int mt = 0; mt < 2; mt++)
#pragma unroll
        for (int nt = 0; nt < 4; nt++) {
            const int j = wn * 16 + nt * 4 + fc;
            const float bfA = __ldg(Ufb + j), bfB = __ldg(Ufb + 128 + j);
            const int kgA = j >> 3, khalf2 = ((j & 7) >= 4) ? 2 : 0;
#pragma unroll
            for (int half = 0; half < 2; half++) {
                int r = mt * 16 + fr + half * 8;
                float fA = sigm(acc[mt][nt][half * 2] + bfA);
                float fB = sigm(acc[mt][nt][half * 2 + 1] + bfB);
                float hA = __ldg(hcg + r * 256 + j);
                float hB = __ldg(hcg + r * 256 + 128 + j);
                float gA = fA * hA, gB = fB * hB;
                int q = khalf2 + half;
                int base = (mt * 32) * 128 + lane * 4 + q;
                sAf[base + kgA * 128]        = tf32r(gA);
                sAf[base + (kgA + 16) * 128] = tf32r(gB);
                sFG[r * FS + j]       = fA + fB;   // fsum
                sFG[r * FS + 128 + j] = gA + gB;   // gsum (exact fp32)
            }
        }
    __syncthreads();   // g/fsum visible to all warps

    // phase 2: v = g @ Uh
    float ac2[2][2][4];
#pragma unroll
    for (int mt = 0; mt < 2; mt++)
#pragma unroll
        for (int nt = 0; nt < 2; nt++)
#pragma unroll
            for (int q = 0; q < 4; q++) ac2[mt][nt][q] = 0.f;

#pragma unroll 4
    for (int kg = 0; kg < 32; kg++) {
        float4 av[2];
#pragma unroll
        for (int mt = 0; mt < 2; mt++)
            av[mt] = *(const float4*)(sAf + ((mt * 32 + kg) * 32 + lane) * 4);
#pragma unroll
        for (int nt = 0; nt < 2; nt++) {
            float2 bv = __ldg((const float2*)(d_Uh + ((kg * 16 + wn * 2 + nt) * 32 + lane) * 2));
#pragma unroll
            for (int mt = 0; mt < 2; mt++)
                mma8(ac2[mt][nt], (const uint32_t*)&av[mt], (const uint32_t*)&bv);
        }
    }

    // epilogue 2 (guarded stores)
#pragma unroll
    for (int mt = 0; mt < 2; mt++)
#pragma unroll
        for (int nt = 0; nt < 2; nt++) {
            int lr0 = mt * 16 + fr;
            int lr1 = lr0 + 8;
            int col = wn * 16 + nt * 8 + 2 * fc;
            float bh0 = __ldg(Uhb + col), bh1 = __ldg(Uhb + col + 1);
            const float* a = ac2[mt][nt];
            if (lr0 < cnt) {
                float o00 = (1.f - sFG[lr0 * FS + col])     * tanhf(a[0] + bh0) + sFG[lr0 * FS + col + 128];
                float o01 = (1.f - sFG[lr0 * FS + col + 1]) * tanhf(a[1] + bh1) + sFG[lr0 * FS + col + 129];
                *(float2*)(outbase + (size_t)lr0 * HD + col) = make_float2(o00, o01);
            }
            if (lr1 < cnt) {
                float o10 = (1.f - sFG[lr1 * FS + col])     * tanhf(a[2] + bh0) + sFG[lr1 * FS + col + 128];
                float o11 = (1.f - sFG[lr1 * FS + col + 1]) * tanhf(a[3] + bh1) + sFG[lr1 * FS + col + 129];
                *(float2*)(outbase + (size_t)lr1 * HD + col) = make_float2(o10, o11);
            }
        }
}

// --------------------------------------------------------------------------
// Level kernel (l >= 6): 32 parents/CTA, 256 threads, 2 CTAs/SM.
// --------------------------------------------------------------------------
__global__ __launch_bounds__(256, 2) void level_mma_k(
    const float* __restrict__ Ufb, const float* __restrict__ Uhb,
    float* __restrict__ h, int start)
{
    extern __shared__ float sm[];
    float* sAf = sm;
    float* sFG = sm + L_FG;

    const int tid = threadIdx.x, lane = tid & 31, wn = tid >> 5;
    const int batch = blockIdx.y;
    const int node0 = start + blockIdx.x * 32;
    const float* hcg = h + ((size_t)batch * NN + 2 * node0 + 1) * HD;
    float* outb = h + ((size_t)batch * NN + node0) * HD;

    mgu_tile32(sAf, sFG, hcg, outb, 32, Ufb, Uhb, tid, lane, wn);
}

// --------------------------------------------------------------------------
// Tail kernel: one CTA per batch walks levels 5..0 (63 nodes) internally.
// __syncthreads orders each level's global writes before next level's reads.
// --------------------------------------------------------------------------
__global__ __launch_bounds__(256, 2) void tail_k(
    const float* __restrict__ Ufb, const float* __restrict__ Uhb,
    float* __restrict__ h)
{
    extern __shared__ float sm[];
    float* sAf = sm;
    float* sFG = sm + L_FG;

    const int tid = threadIdx.x, lane = tid & 31, wn = tid >> 5;
    const int batch = blockIdx.x;

    for (int l = 5; l >= 0; --l) {
        const int start = (1 << l) - 1, cnt = 1 << l;
        const float* hcg = h + ((size_t)batch * NN + 2 * start + 1) * HD;
        float* outb = h + ((size_t)batch * NN + start) * HD;
        mgu_tile32(sAf, sFG, hcg, outb, cnt, Ufb, Uhb, tid, lane, wn);
        __syncthreads();   // level writes visible + sAf free before reuse
    }
}

// --------------------------------------------------------------------------
// Init kernel: 64 leaf rows/CTA, 512 threads, 66KB smem, 2 CTAs/SM.
// --------------------------------------------------------------------------
__global__ __launch_bounds__(512, 2) void init_mma_k(
    const float* __restrict__ x, const float* __restrict__ Wb, float* __restrict__ h)
{
    extern __shared__ float sm[];
    float* sAf = sm;            // [rowblk(4)][kg(16)][lane(32)][4] = 8192 floats
    float* stg = sm + I_STG;    // 64 x 132 output staging

    const int tid = threadIdx.x, lane = tid & 31, wid = tid >> 5;
    const int batch = blockIdx.y;
    const int row0 = blockIdx.x * 64;   // leaf-local
    const float* xg = x + ((size_t)batch * NN + 16383 + row0) * HD;

    for (int i = tid; i < 2048; i += 512) {
        float4 v = ((const float4*)xg)[i];
        int r = i >> 5, c = (i & 31) << 2;
        int q = (((c & 7) >= 4) ? 2 : 0) + (((r & 15) >= 8) ? 1 : 0);
        float* dst = sAf + (((r >> 4) * 16 + (c >> 3)) * 32 + (r & 7) * 4) * 4 + q;
        dst[0]  = tf32r(v.x);
        dst[4]  = tf32r(v.y);
        dst[8]  = tf32r(v.z);
        dst[12] = tf32r(v.w);
    }
    __syncthreads();

    const int wm = wid & 1, wn = wid >> 1;
    const int wr = wm * 32;
    const int fr = lane >> 2, fc = lane & 3;

    float acc[2][4][4];
#pragma unroll
    for (int mt = 0; mt < 2; mt++)
#pragma unroll
        for (int nt = 0; nt < 4; nt++)
#pragma unroll
            for (int q = 0; q < 4; q++) acc[mt][nt][q] = 0.f;

#pragma unroll 4
    for (int kg = 0; kg < 16; kg++) {
        float4 av[2];
#pragma unroll
        for (int mt = 0; mt < 2; mt++)
            av[mt] = *(const float4*)(sAf + (((wm * 2 + mt) * 16 + kg) * 32 + lane) * 4);
#pragma unroll
        for (int nt = 0; nt < 4; nt++) {
            float2 bv = __ldg((const float2*)(d_W0 + ((kg * 32 + wn * 4 + nt) * 32 + lane) * 2));
#pragma unroll
            for (int mt = 0; mt < 2; mt++)
                mma8(acc[mt][nt], (const uint32_t*)&av[mt], (const uint32_t*)&bv);
        }
    }

#pragma unroll
    for (int mt = 0; mt < 2; mt++)
#pragma unroll
        for (int nt = 0; nt < 4; nt++) {
            const int j = wn * 16 + nt * 4 + fc;
            const float bA = __ldg(Wb + j), bB = __ldg(Wb + 128 + j);
#pragma unroll
            for (int half = 0; half < 2; half++) {
                int r = wr + mt * 16 + fr + half * 8;
                float f0 = sigm(acc[mt][nt][half * 2] + bA);
                float c0 = tanhf(acc[mt][nt][half * 2 + 1] + bB);
                stg[r * 132 + j] = (1.f - f0) * c0;
            }
        }
    __syncthreads();

    for (int i = tid; i < 2048; i += 512) {
        int r = i >> 5, c = (i & 31) << 2;
        float4 v = *(const float4*)(stg + r * 132 + c);
        *(float4*)(h + ((size_t)batch * NN + 16383 + row0 + r) * HD + c) = v;
    }
}

// --------------------------------------------------------------------------
extern "C" void kernel_launch(void* const* d_in, const int* in_sizes, int n_in,
                              void* d_out, int out_size)
{
    const float* x   = (const float*)d_in[0];
    const float* Ww  = (const float*)d_in[1];
    const float* Wb  = (const float*)d_in[2];
    const float* Ufw = (const float*)d_in[3];
    const float* Ufb = (const float*)d_in[4];
    const float* Uhw = (const float*)d_in[5];
    const float* Uhb = (const float*)d_in[6];
    float* h = (float*)d_out;

    cudaFuncSetAttribute(level_mma_k, cudaFuncAttributeMaxDynamicSharedMemorySize, SMEM_LVL);
    cudaFuncSetAttribute(tail_k,      cudaFuncAttributeMaxDynamicSharedMemorySize, SMEM_LVL);
    cudaFuncSetAttribute(init_mma_k,  cudaFuncAttributeMaxDynamicSharedMemorySize, SMEM_INI);

    prep_k<<<128, 256>>>(Ww, Ufw, Uhw);
    init_mma_k<<<dim3(256, NB), 512, SMEM_INI>>>(x, Wb, h);

    for (int l = 13; l >= 6; --l) {
        int start = (1 << l) - 1, cnt = 1 << l;
        level_mma_k<<<dim3(cnt / 32, NB), 256, SMEM_LVL>>>(Ufb, Uhb, h, start);
    }
    tail_k<<<NB, 256, SMEM_LVL>>>(Ufb, Uhb, h);
}

// round 16
// speedup vs baseline: 1.1400x; 1.0866x over previous
#include <cuda_runtime.h>
#include <math.h>
#include <stdint.h>

#define NB 16
#define NN 32767
#define HD 128

// Fragment-packed tf32 weights in GLOBAL, layout [kg][nb][lane][2]:
//   elem[((kg*NBLK + nb)*32 + lane)*2 + p] = W[kg*8 + (lane&3) + 4p][col(nb,lane>>2)]
// d_Uf, d_W0 (NBLK=32): col = pairwise INTERLEAVE of (j, 128+j): cI=2j <-> j, 2j+1 <-> 128+j
// d_Uh (NBLK=16):       plain col = nb*8 + (lane>>2)
__device__ float d_Uf[256 * 256];   // kg 0..31
__device__ float d_Uh[256 * 128];   // kg 0..31
__device__ float d_W0[128 * 256];   // kg 0..15

__device__ __forceinline__ float sigm(float v) { return 1.f / (1.f + expf(-v)); }
__device__ __forceinline__ float tf32r(float x) {
    float r; asm("cvt.rna.tf32.f32 %0, %1;" : "=f"(r) : "f"(x)); return r;
}
__device__ __forceinline__ void mma8(float* d, const uint32_t* a, const uint32_t* b) {
    asm volatile(
        "mma.sync.aligned.m16n8k8.row.col.f32.tf32.tf32.f32 "
        "{%0,%1,%2,%3}, {%4,%5,%6,%7}, {%8,%9}, {%0,%1,%2,%3};"
        : "+f"(d[0]), "+f"(d[1]), "+f"(d[2]), "+f"(d[3])
        : "r"(a[0]), "r"(a[1]), "r"(a[2]), "r"(a[3]), "r"(b[0]), "r"(b[1]));
}

#define FS 260
// level smem (floats): sAf 8192 | sFG 8320   (32-row tile)
#define L_FG 8192
#define SMEM_LVL ((8192 + 8320) * 4)       // 66048 B -> 2 CTAs/SM @256thr
// init smem (floats): sAf 8192 | stg 8448
#define I_STG 8192
#define SMEM_INI ((8192 + 8448) * 4)       // 66560 B -> 2 CTAs/SM @512thr

// --------------------------------------------------------------------------
__global__ void prep_k(const float* __restrict__ Ww, const float* __restrict__ Ufw,
                       const float* __restrict__ Uhw)
{
    int i0 = blockIdx.x * blockDim.x + threadIdx.x, st = gridDim.x * blockDim.x;
    for (int idx = i0; idx < 131072; idx += st) {
        if (idx < 65536) {              // d_Uf
            int p = idx & 1, lane = (idx >> 1) & 31, nb = (idx >> 6) & 31, kg = idx >> 11;
            int k = kg * 8 + (lane & 3) + 4 * p;
            int cI = nb * 8 + (lane >> 2);
            int oc = (cI >> 1) + ((cI & 1) << 7);
            d_Uf[idx] = tf32r(Ufw[k * 256 + oc]);
        } else if (idx < 98304) {       // d_Uh
            int j = idx - 65536;
            int p = j & 1, lane = (j >> 1) & 31, nb = (j >> 6) & 15, kg = j >> 10;
            int k = kg * 8 + (lane & 3) + 4 * p;
            int n = nb * 8 + (lane >> 2);
            d_Uh[j] = tf32r(Uhw[k * 128 + n]);
        } else {                        // d_W0
            int j = idx - 98304;
            int p = j & 1, lane = (j >> 1) & 31, nb = (j >> 6) & 31, kg = j >> 11;
            int k = kg * 8 + (lane & 3) + 4 * p;
            int cI = nb * 8 + (lane >> 2);
            int oc = (cI >> 1) + ((cI & 1) << 7);
            d_W0[j] = tf32r(Ww[k * 256 + oc]);
        }
    }
}

// --------------------------------------------------------------------------
// Shared 32-row MGU tile body: 256 threads, 8 warps all in N, mt=2.
// Both MMA phases software-pipelined: kg+1 operands prefetched into regs
// before kg's MMAs issue (hides B L2 latency + A LDS latency).
// --------------------------------------------------------------------------
__device__ __forceinline__ void mgu_tile32(
    float* sAf, float* sFG, const float* hcg, float* outbase, int cnt,
    const float* __restrict__ Ufb, const float* __restrict__ Uhb,
    int tid, int lane, int wn)
{
    // load A = hc (32x256) into packed fragment layout, tf32-rounded
    for (int i = tid; i < 2048; i += 256) {
        float4 v = ((const float4*)hcg)[i];
        int r = i >> 6, c = (i & 63) << 2;
        int q = (((c & 7) >= 4) ? 2 : 0) + (((r & 15) >= 8) ? 1 : 0);
        float* dst = sAf + (((r >> 4) * 32 + (c >> 3)) * 32 + (r & 7) * 4) * 4 + q;
        dst[0]  = tf32r(v.x);
        dst[4]  = tf32r(v.y);
        dst[8]  = tf32r(v.z);
        dst[12] = tf32r(v.w);
    }
    __syncthreads();

    const int fr = lane >> 2, fc = lane & 3;

    // ---------------- phase 1: u = hc @ Uf (interleaved cols), pipelined ----
    float acc[2][4][4];
#pragma unroll
    for (int mt = 0; mt < 2; mt++)
#pragma unroll
        for (int nt = 0; nt < 4; nt++)
#pragma unroll
            for (int q = 0; q < 4; q++) acc[mt][nt][q] = 0.f;

    {
        float4 av[2];
        float2 bv[4];
#pragma unroll
        for (int mt = 0; mt < 2; mt++)
            av[mt] = *(const float4*)(sAf + ((mt * 32 + 0) * 32 + lane) * 4);
#pragma unroll
        for (int nt = 0; nt < 4; nt++)
            bv[nt] = __ldg((const float2*)(d_Uf + ((0 * 32 + wn * 4 + nt) * 32 + lane) * 2));

#pragma unroll
        for (int kg = 0; kg < 32; kg++) {
            float4 avn[2];
            float2 bvn[4];
            if (kg < 31) {
#pragma unroll
                for (int mt = 0; mt < 2; mt++)
                    avn[mt] = *(const float4*)(sAf + ((mt * 32 + kg + 1) * 32 + lane) * 4);
#pragma unroll
                for (int nt = 0; nt < 4; nt++)
                    bvn[nt] = __ldg((const float2*)(d_Uf + (((kg + 1) * 32 + wn * 4 + nt) * 32 + lane) * 2));
            }
#pragma unroll
            for (int nt = 0; nt < 4; nt++)
#pragma unroll
                for (int mt = 0; mt < 2; mt++)
                    mma8(acc[mt][nt], (const uint32_t*)&av[mt], (const uint32_t*)&bv[nt]);
            if (kg < 31) {
#pragma unroll
                for (int mt = 0; mt < 2; mt++) av[mt] = avn[mt];
#pragma unroll
                for (int nt = 0; nt < 4; nt++) bv[nt] = bvn[nt];
            }
        }
    }
    __syncthreads();   // phase-1 A reads complete before g overwrite

    // epilogue 1
#pragma unroll
    for (int mt = 0; mt < 2; mt++)
#pragma unroll
        for (int nt = 0; nt < 4; nt++) {
            const int j = wn * 16 + nt * 4 + fc;
            const float bfA = __ldg(Ufb + j), bfB = __ldg(Ufb + 128 + j);
            const int kgA = j >> 3, khalf2 = ((j & 7) >= 4) ? 2 : 0;
#pragma unroll
            for (int half = 0; half < 2; half++) {
                int r = mt * 16 + fr + half * 8;
                float fA = sigm(acc[mt][nt][half * 2] + bfA);
                float fB = sigm(acc[mt][nt][half * 2 + 1] + bfB);
                float hA = __ldg(hcg + r * 256 + j);
                float hB = __ldg(hcg + r * 256 + 128 + j);
                float gA = fA * hA, gB = fB * hB;
                int q = khalf2 + half;
                int base = (mt * 32) * 128 + lane * 4 + q;
                sAf[base + kgA * 128]        = tf32r(gA);
                sAf[base + (kgA + 16) * 128] = tf32r(gB);
                sFG[r * FS + j]       = fA + fB;   // fsum
                sFG[r * FS + 128 + j] = gA + gB;   // gsum (exact fp32)
            }
        }
    __syncthreads();   // g/fsum visible to all warps

    // ---------------- phase 2: v = g @ Uh, pipelined ----------------
    float ac2[2][2][4];
#pragma unroll
    for (int mt = 0; mt < 2; mt++)
#pragma unroll
        for (int nt = 0; nt < 2; nt++)
#pragma unroll
            for (int q = 0; q < 4; q++) ac2[mt][nt][q] = 0.f;

    {
        float4 av[2];
        float2 bv[2];
#pragma unroll
        for (int mt = 0; mt < 2; mt++)
            av[mt] = *(const float4*)(sAf + ((mt * 32 + 0) * 32 + lane) * 4);
#pragma unroll
        for (int nt = 0; nt < 2; nt++)
            bv[nt] = __ldg((const float2*)(d_Uh + ((0 * 16 + wn * 2 + nt) * 32 + lane) * 2));

#pragma unroll
        for (int kg = 0; kg < 32; kg++) {
            float4 avn[2];
            float2 bvn[2];
            if (kg < 31) {
#pragma unroll
                for (int mt = 0; mt < 2; mt++)
                    avn[mt] = *(const float4*)(sAf + ((mt * 32 + kg + 1) * 32 + lane) * 4);
#pragma unroll
                for (int nt = 0; nt < 2; nt++)
                    bvn[nt] = __ldg((const float2*)(d_Uh + (((kg + 1) * 16 + wn * 2 + nt) * 32 + lane) * 2));
            }
#pragma unroll
            for (int nt = 0; nt < 2; nt++)
#pragma unroll
                for (int mt = 0; mt < 2; mt++)
                    mma8(ac2[mt][nt], (const uint32_t*)&av[mt], (const uint32_t*)&bv[nt]);
            if (kg < 31) {
#pragma unroll
                for (int mt = 0; mt < 2; mt++) av[mt] = avn[mt];
#pragma unroll
                for (int nt = 0; nt < 2; nt++) bv[nt] = bvn[nt];
            }
        }
    }

    // epilogue 2 (guarded stores)
#pragma unroll
    for (int mt = 0; mt < 2; mt++)
#pragma unroll
        for (int nt = 0; nt < 2; nt++) {
            int lr0 = mt * 16 + fr;
            int lr1 = lr0 + 8;
            int col = wn * 16 + nt * 8 + 2 * fc;
            float bh0 = __ldg(Uhb + col), bh1 = __ldg(Uhb + col + 1);
            const float* a = ac2[mt][nt];
            if (lr0 < cnt) {
                float o00 = (1.f - sFG[lr0 * FS + col])     * tanhf(a[0] + bh0) + sFG[lr0 * FS + col + 128];
                float o01 = (1.f - sFG[lr0 * FS + col + 1]) * tanhf(a[1] + bh1) + sFG[lr0 * FS + col + 129];
                *(float2*)(outbase + (size_t)lr0 * HD + col) = make_float2(o00, o01);
            }
            if (lr1 < cnt) {
                float o10 = (1.f - sFG[lr1 * FS + col])     * tanhf(a[2] + bh0) + sFG[lr1 * FS + col + 128];
                float o11 = (1.f - sFG[lr1 * FS + col + 1]) * tanhf(a[3] + bh1) + sFG[lr1 * FS + col + 129];
                *(float2*)(outbase + (size_t)lr1 * HD + col) = make_float2(o10, o11);
            }
        }
}

// --------------------------------------------------------------------------
// Level kernel (l >= 6): 32 parents/CTA, 256 threads, 2 CTAs/SM.
// --------------------------------------------------------------------------
__global__ __launch_bounds__(256, 2) void level_mma_k(
    const float* __restrict__ Ufb, const float* __restrict__ Uhb,
    float* __restrict__ h, int start)
{
    extern __shared__ float sm[];
    float* sAf = sm;
    float* sFG = sm + L_FG;

    const int tid = threadIdx.x, lane = tid & 31, wn = tid >> 5;
    const int batch = blockIdx.y;
    const int node0 = start + blockIdx.x * 32;
    const float* hcg = h + ((size_t)batch * NN + 2 * node0 + 1) * HD;
    float* outb = h + ((size_t)batch * NN + node0) * HD;

    mgu_tile32(sAf, sFG, hcg, outb, 32, Ufb, Uhb, tid, lane, wn);
}

// --------------------------------------------------------------------------
// Tail kernel: one CTA per batch walks levels 5..0 (63 nodes) internally.
// --------------------------------------------------------------------------
__global__ __launch_bounds__(256, 2) void tail_k(
    const float* __restrict__ Ufb, const float* __restrict__ Uhb,
    float* __restrict__ h)
{
    extern __shared__ float sm[];
    float* sAf = sm;
    float* sFG = sm + L_FG;

    const int tid = threadIdx.x, lane = tid & 31, wn = tid >> 5;
    const int batch = blockIdx.x;

    for (int l = 5; l >= 0; --l) {
        const int start = (1 << l) - 1, cnt = 1 << l;
        const float* hcg = h + ((size_t)batch * NN + 2 * start + 1) * HD;
        float* outb = h + ((size_t)batch * NN + start) * HD;
        mgu_tile32(sAf, sFG, hcg, outb, cnt, Ufb, Uhb, tid, lane, wn);
        __syncthreads();   // level writes visible + sAf free before reuse
    }
}

// --------------------------------------------------------------------------
// Init kernel: 64 leaf rows/CTA, 512 threads, 66KB smem, 2 CTAs/SM.
// Pipelined like the level kernel.
// --------------------------------------------------------------------------
__global__ __launch_bounds__(512, 2) void init_mma_k(
    const float* __restrict__ x, const float* __restrict__ Wb, float* __restrict__ h)
{
    extern __shared__ float sm[];
    float* sAf = sm;            // [rowblk(4)][kg(16)][lane(32)][4] = 8192 floats
    float* stg = sm + I_STG;    // 64 x 132 output staging

    const int tid = threadIdx.x, lane = tid & 31, wid = tid >> 5;
    const int batch = blockIdx.y;
    const int row0 = blockIdx.x * 64;   // leaf-local
    const float* xg = x + ((size_t)batch * NN + 16383 + row0) * HD;

    for (int i = tid; i < 2048; i += 512) {
        float4 v = ((const float4*)xg)[i];
        int r = i >> 5, c = (i & 31) << 2;
        int q = (((c & 7) >= 4) ? 2 : 0) + (((r & 15) >= 8) ? 1 : 0);
        float* dst = sAf + (((r >> 4) * 16 + (c >> 3)) * 32 + (r & 7) * 4) * 4 + q;
        dst[0]  = tf32r(v.x);
        dst[4]  = tf32r(v.y);
        dst[8]  = tf32r(v.z);
        dst[12] = tf32r(v.w);
    }
    __syncthreads();

    const int wm = wid & 1, wn = wid >> 1;
    const int wr = wm * 32;
    const int fr = lane >> 2, fc = lane & 3;

    float acc[2][4][4];
#pragma unroll
    for (int mt = 0; mt < 2; mt++)
#pragma unroll
        for (int nt = 0; nt < 4; nt++)
#pragma unroll
            for (int q = 0; q < 4; q++) acc[mt][nt][q] = 0.f;

    {
        float4 av[2];
        float2 bv[4];
#pragma unroll
        for (int mt = 0; mt < 2; mt++)
            av[mt] = *(const float4*)(sAf + (((wm * 2 + mt) * 16 + 0) * 32 + lane) * 4);
#pragma unroll
        for (int nt = 0; nt < 4; nt++)
            bv[nt] = __ldg((const float2*)(d_W0 + ((0 * 32 + wn * 4 + nt) * 32 + lane) * 2));

#pragma unroll
        for (int kg = 0; kg < 16; kg++) {
            float4 avn[2];
            float2 bvn[4];
            if (kg < 15) {
#pragma unroll
                for (int mt = 0; mt < 2; mt++)
                    avn[mt] = *(const float4*)(sAf + (((wm * 2 + mt) * 16 + kg + 1) * 32 + lane) * 4);
#pragma unroll
                for (int nt = 0; nt < 4; nt++)
                    bvn[nt] = __ldg((const float2*)(d_W0 + (((kg + 1) * 32 + wn * 4 + nt) * 32 + lane) * 2));
            }
#pragma unroll
            for (int nt = 0; nt < 4; nt++)
#pragma unroll
                for (int mt = 0; mt < 2; mt++)
                    mma8(acc[mt][nt], (const uint32_t*)&av[mt], (const uint32_t*)&bv[nt]);
            if (kg < 15) {
#pragma unroll
                for (int mt = 0; mt < 2; mt++) av[mt] = avn[mt];
#pragma unroll
                for (int nt = 0; nt < 4; nt++) bv[nt] = bvn[nt];
            }
        }
    }

#pragma unroll
    for (int mt = 0; mt < 2; mt++)
#pragma unroll
        for (int nt = 0; nt < 4; nt++) {
            const int j = wn * 16 + nt * 4 + fc;
            const float bA = __ldg(Wb + j), bB = __ldg(Wb + 128 + j);
#pragma unroll
            for (int half = 0; half < 2; half++) {
                int r = wr + mt * 16 + fr + half * 8;
                float f0 = sigm(acc[mt][nt][half * 2] + bA);
                float c0 = tanhf(acc[mt][nt][half * 2 + 1] + bB);
                stg[r * 132 + j] = (1.f - f0) * c0;
            }
        }
    __syncthreads();

    for (int i = tid; i < 2048; i += 512) {
        int r = i >> 5, c = (i & 31) << 2;
        float4 v = *(const float4*)(stg + r * 132 + c);
        *(float4*)(h + ((size_t)batch * NN + 16383 + row0 + r) * HD + c) = v;
    }
}

// --------------------------------------------------------------------------
extern "C" void kernel_launch(void* const* d_in, const int* in_sizes, int n_in,
                              void* d_out, int out_size)
{
    const float* x   = (const float*)d_in[0];
    const float* Ww  = (const float*)d_in[1];
    const float* Wb  = (const float*)d_in[2];
    const float* Ufw = (const float*)d_in[3];
    const float* Ufb = (const float*)d_in[4];
    const float* Uhw = (const float*)d_in[5];
    const float* Uhb = (const float*)d_in[6];
    float* h = (float*)d_out;

    cudaFuncSetAttribute(level_mma_k, cudaFuncAttributeMaxDynamicSharedMemorySize, SMEM_LVL);
    cudaFuncSetAttribute(tail_k,      cudaFuncAttributeMaxDynamicSharedMemorySize, SMEM_LVL);
    cudaFuncSetAttribute(init_mma_k,  cudaFuncAttributeMaxDynamicSharedMemorySize, SMEM_INI);

    prep_k<<<128, 256>>>(Ww, Ufw, Uhw);
    init_mma_k<<<dim3(256, NB), 512, SMEM_INI>>>(x, Wb, h);

    for (int l = 13; l >= 6; --l) {
        int start = (1 << l) - 1, cnt = 1 << l;
        level_mma_k<<<dim3(cnt / 32, NB), 256, SMEM_LVL>>>(Ufb, Uhb, h, start);
    }
    tail_k<<<NB, 256, SMEM_LVL>>>(Ufb, Uhb, h);
}